// round 11
// baseline (speedup 1.0000x reference)
#include <cuda_runtime.h>
#include <cuda_fp16.h>

#define NN   100000
#define EE   20000
#define NNZV 1000000
#define DIM  128

struct alignas(8) h4 { __half2 a, b; };

// ---- scratch: ~50 MB device globals ----
__device__ int    g_ecnt[EE];
__device__ int    g_ncnt[NN];
__device__ int    g_eoff[EE + 1];
__device__ int    g_noff[NN + 1];
__device__ int    g_ecur[EE];
__device__ int    g_ncur[NN];
__device__ int    g_pe[64];
__device__ int    g_pn[128];
__device__ int    g_erows[NNZV];      // CSR by edge: node idx per slot (4 MB)
__device__ int    g_ncols[NNZV];      // CSC by node: edge idx per slot (4 MB)
__device__ __half g_xh[NN * DIM];     // 25.6 MB  fp16(dv^-1/2 * X)
__device__ float  g_m[EE * DIM];      // 10.24 MB fp32 hyperedge features
__device__ __half g_m2h[EE * DIM];    // 5.12 MB  fp16 (m @ W)
__device__ float  g_dvis[NN];         // dv^-1/2
__device__ float  g_deinv[EE];        // de^-1

// ---- 1) fused prep: counters+scales, X->fp16, degree histogram ----
__global__ void prep_kernel(const float* __restrict__ X,
                            const float* __restrict__ dv,
                            const float* __restrict__ de,
                            const int*   __restrict__ rows,
                            const int*   __restrict__ cols) {
    int tid = blockIdx.x * blockDim.x + threadIdx.x;
    int stride = gridDim.x * blockDim.x;
    for (int i = tid; i < NN; i += stride) {
        g_ncnt[i] = 0;
        g_dvis[i] = rsqrtf(__ldg(dv + i));
    }
    for (int i = tid; i < EE; i += stride) {
        g_ecnt[i] = 0;
        g_deinv[i] = 1.0f / __ldg(de + i);
    }
    // X -> fp16 with dv^-1/2 folded (HBM-stream-bound)
    const float4* X4 = reinterpret_cast<const float4*>(X);
    h4* Xh = reinterpret_cast<h4*>(g_xh);
    const int UNITS = NN * (DIM / 4);
    for (int u = tid; u < UNITS; u += stride) {
        int r = u >> 5;
        float s = rsqrtf(__ldg(dv + r));
        float4 x = __ldg(X4 + u);
        h4 o;
        o.a = __floats2half2_rn(s * x.x, s * x.y);
        o.b = __floats2half2_rn(s * x.z, s * x.w);
        Xh[u] = o;
    }
    // degree histogram (L2-atomic-bound; overlaps the stream above), MLP=4
    // NOTE: counters are zeroed by THIS kernel before this loop only within a
    // thread's own view — ordering across threads is guaranteed because the
    // zero loops cover ALL of g_ncnt/g_ecnt before any thread reaches here
    // only if grid-stride aligns... it does NOT. So zero via a different rule:
    // counters were zeroed at the END of the previous graph replay? No.
    // -> Safe approach: histogram into the cursors instead (g_ecur/g_ncur),
    //    which are consumed only after scanC rewrites them. But they must be
    //    zeroed too. Instead: require this kernel's zero phase to complete
    //    before counting -> use a separate kernel boundary. We keep count in
    //    a second kernel below. (This loop intentionally removed.)
}

// ---- 2) histogram degrees (MLP=4) ----
__global__ void count_kernel(const int* __restrict__ rows,
                             const int* __restrict__ cols) {
    int tid = blockIdx.x * blockDim.x + threadIdx.x;
    int stride = gridDim.x * blockDim.x;
    int i = tid * 4;
    int step = stride * 4;
    for (; i + 4 <= NNZV; i += step) {
        int c0 = __ldg(cols + i), c1 = __ldg(cols + i + 1);
        int c2 = __ldg(cols + i + 2), c3 = __ldg(cols + i + 3);
        int r0 = __ldg(rows + i), r1 = __ldg(rows + i + 1);
        int r2 = __ldg(rows + i + 2), r3 = __ldg(rows + i + 3);
        atomicAdd(&g_ecnt[c0], 1); atomicAdd(&g_ecnt[c1], 1);
        atomicAdd(&g_ecnt[c2], 1); atomicAdd(&g_ecnt[c3], 1);
        atomicAdd(&g_ncnt[r0], 1); atomicAdd(&g_ncnt[r1], 1);
        atomicAdd(&g_ncnt[r2], 1); atomicAdd(&g_ncnt[r3], 1);
    }
    for (; i < NNZV; i++) {
        atomicAdd(&g_ecnt[__ldg(cols + i)], 1);
        atomicAdd(&g_ncnt[__ldg(rows + i)], 1);
    }
}

// ---- 3) fused block scans: blocks [0,NBE) edges, [NBE,NBE+NBN) nodes ----
#define NBE 20
#define NBN 98
__device__ __forceinline__ void block_scan_body(const int* cnt, int* off,
                                                int* partial, int len, int blk) {
    __shared__ int ws[32];
    int tid = threadIdx.x;
    int lane = tid & 31, wid = tid >> 5;
    int i = blk * 1024 + tid;
    int v = (i < len) ? cnt[i] : 0;
    int sum = v;
#pragma unroll
    for (int d = 1; d < 32; d <<= 1) {
        int t = __shfl_up_sync(0xffffffffu, sum, d);
        if (lane >= d) sum += t;
    }
    if (lane == 31) ws[wid] = sum;
    __syncthreads();
    if (wid == 0) {
        int wsum = ws[lane];
#pragma unroll
        for (int d = 1; d < 32; d <<= 1) {
            int t = __shfl_up_sync(0xffffffffu, wsum, d);
            if (lane >= d) wsum += t;
        }
        ws[lane] = wsum;
    }
    __syncthreads();
    int incl = sum + (wid > 0 ? ws[wid - 1] : 0);
    if (i < len) off[i] = incl - v;
    if (tid == 1023) partial[blk] = incl;
}
__global__ void scanA_kernel() {
    if (blockIdx.x < NBE)
        block_scan_body(g_ecnt, g_eoff, g_pe, EE, blockIdx.x);
    else
        block_scan_body(g_ncnt, g_noff, g_pn, NN, blockIdx.x - NBE);
}

__global__ void scanB_kernel() {
    if (threadIdx.x == 0) {
        int run = 0;
        for (int b = 0; b < NBE; b++) { int t = g_pe[b]; g_pe[b] = run; run += t; }
    }
    if (threadIdx.x == 1) {
        int run = 0;
        for (int b = 0; b < NBN; b++) { int t = g_pn[b]; g_pn[b] = run; run += t; }
    }
}

__global__ void scanC_kernel() {
    int tid = blockIdx.x * blockDim.x + threadIdx.x;
    int stride = gridDim.x * blockDim.x;
    for (int i = tid; i < EE; i += stride) {
        int o = g_eoff[i] + g_pe[i >> 10];
        g_eoff[i] = o;
        g_ecur[i] = o;
    }
    for (int i = tid; i < NN; i += stride) {
        int o = g_noff[i] + g_pn[i >> 10];
        g_noff[i] = o;
        g_ncur[i] = o;
    }
    if (tid == 0) { g_eoff[EE] = NNZV; g_noff[NN] = NNZV; }
}

// ---- 6) fill buckets (MLP=4 batches) ----
__global__ void fill_kernel(const int* __restrict__ rows,
                            const int* __restrict__ cols) {
    int tid = blockIdx.x * blockDim.x + threadIdx.x;
    int stride = gridDim.x * blockDim.x;
    int i = tid * 4;
    int step = stride * 4;
    for (; i + 4 <= NNZV; i += step) {
        int r0 = __ldg(rows + i), r1 = __ldg(rows + i + 1);
        int r2 = __ldg(rows + i + 2), r3 = __ldg(rows + i + 3);
        int c0 = __ldg(cols + i), c1 = __ldg(cols + i + 1);
        int c2 = __ldg(cols + i + 2), c3 = __ldg(cols + i + 3);
        int p0 = atomicAdd(&g_ecur[c0], 1);
        int p1 = atomicAdd(&g_ecur[c1], 1);
        int p2 = atomicAdd(&g_ecur[c2], 1);
        int p3 = atomicAdd(&g_ecur[c3], 1);
        g_erows[p0] = r0; g_erows[p1] = r1; g_erows[p2] = r2; g_erows[p3] = r3;
        int q0 = atomicAdd(&g_ncur[r0], 1);
        int q1 = atomicAdd(&g_ncur[r1], 1);
        int q2 = atomicAdd(&g_ncur[r2], 1);
        int q3 = atomicAdd(&g_ncur[r3], 1);
        g_ncols[q0] = c0; g_ncols[q1] = c1; g_ncols[q2] = c2; g_ncols[q3] = c3;
    }
    for (; i < NNZV; i++) {
        int r = __ldg(rows + i);
        int c = __ldg(cols + i);
        int p = atomicAdd(&g_ecur[c], 1);
        g_erows[p] = r;
        int q = atomicAdd(&g_ncur[r], 1);
        g_ncols[q] = c;
    }
}

// ---- 7) phase1: m[e] = de^-1 * Σ_{r∈e} Xh[r]  (warp/edge, fp16, MLP=8) ----
__global__ __launch_bounds__(256)
void phase1_kernel() {
    int e = (blockIdx.x * blockDim.x + threadIdx.x) >> 5;
    if (e >= EE) return;
    int lane = threadIdx.x & 31;
    const h4* Xh = reinterpret_cast<const h4*>(g_xh);

    int i = g_eoff[e], end = g_eoff[e + 1];
    float4 acc = make_float4(0.f, 0.f, 0.f, 0.f);
    for (; i + 8 <= end; i += 8) {
        int r[8];
#pragma unroll
        for (int u = 0; u < 8; u++) r[u] = g_erows[i + u];
        h4 v[8];
#pragma unroll
        for (int u = 0; u < 8; u++) v[u] = Xh[r[u] * 32 + lane];
#pragma unroll
        for (int u = 0; u < 8; u++) {
            float2 a = __half22float2(v[u].a), b = __half22float2(v[u].b);
            acc.x += a.x; acc.y += a.y; acc.z += b.x; acc.w += b.y;
        }
    }
    if (i + 4 <= end) {
        int r[4];
#pragma unroll
        for (int u = 0; u < 4; u++) r[u] = g_erows[i + u];
        h4 v[4];
#pragma unroll
        for (int u = 0; u < 4; u++) v[u] = Xh[r[u] * 32 + lane];
#pragma unroll
        for (int u = 0; u < 4; u++) {
            float2 a = __half22float2(v[u].a), b = __half22float2(v[u].b);
            acc.x += a.x; acc.y += a.y; acc.z += b.x; acc.w += b.y;
        }
        i += 4;
    }
    for (; i < end; i++) {
        h4 v = Xh[g_erows[i] * 32 + lane];
        float2 a = __half22float2(v.a), b = __half22float2(v.b);
        acc.x += a.x; acc.y += a.y; acc.z += b.x; acc.w += b.y;
    }
    float d = g_deinv[e];
    acc.x *= d; acc.y *= d; acc.z *= d; acc.w *= d;
    *(reinterpret_cast<float4*>(g_m) + e * (DIM / 4) + lane) = acc;
}

// ---- 8) gemmE: M2h = fp16(m @ W)  BM=128, 8x8 micro ----
__global__ __launch_bounds__(256, 1)
void gemmE_kernel(const float* __restrict__ W) {
    extern __shared__ float smem[];
    float* Yt = smem;                 // [DIM][DIM] k-major
    float* Ws = smem + DIM * DIM;     // [DIM][DIM] row-major

    int tid = threadIdx.x;
    int block_row = blockIdx.x * 128;

    for (int i = tid; i < DIM * (DIM / 4); i += 256) {
        int r = i >> 5, c4 = i & 31;
        float4 v = __ldg(reinterpret_cast<const float4*>(W) + r * (DIM / 4) + c4);
        *reinterpret_cast<float4*>(&Ws[r * DIM + c4 * 4]) = v;
    }
    for (int i = tid; i < (DIM / 4) * DIM; i += 256) {
        int r = i & 127, c4 = i >> 7;
        int e = block_row + r;
        float4 v = make_float4(0.f, 0.f, 0.f, 0.f);
        if (e < EE)
            v = *(reinterpret_cast<const float4*>(g_m) + e * (DIM / 4) + c4);
        Yt[(c4 * 4 + 0) * DIM + r] = v.x;
        Yt[(c4 * 4 + 1) * DIM + r] = v.y;
        Yt[(c4 * 4 + 2) * DIM + r] = v.z;
        Yt[(c4 * 4 + 3) * DIM + r] = v.w;
    }
    __syncthreads();

    int tx = tid & 15;
    int ty = tid >> 4;

    float acc[8][8];
#pragma unroll
    for (int i = 0; i < 8; i++)
#pragma unroll
        for (int j = 0; j < 8; j++) acc[i][j] = 0.f;

#pragma unroll 4
    for (int k = 0; k < DIM; k++) {
        float yf[8], wf[8];
        *reinterpret_cast<float4*>(&yf[0]) = *reinterpret_cast<float4*>(&Yt[k * DIM + ty * 8]);
        *reinterpret_cast<float4*>(&yf[4]) = *reinterpret_cast<float4*>(&Yt[k * DIM + ty * 8 + 4]);
        *reinterpret_cast<float4*>(&wf[0]) = *reinterpret_cast<float4*>(&Ws[k * DIM + tx * 8]);
        *reinterpret_cast<float4*>(&wf[4]) = *reinterpret_cast<float4*>(&Ws[k * DIM + tx * 8 + 4]);
#pragma unroll
        for (int i = 0; i < 8; i++)
#pragma unroll
            for (int j = 0; j < 8; j++)
                acc[i][j] += yf[i] * wf[j];
    }

#pragma unroll
    for (int i = 0; i < 8; i++) {
        int e = block_row + ty * 8 + i;
        if (e < EE) {
            alignas(16) __half2 hh[4];
            hh[0] = __floats2half2_rn(acc[i][0], acc[i][1]);
            hh[1] = __floats2half2_rn(acc[i][2], acc[i][3]);
            hh[2] = __floats2half2_rn(acc[i][4], acc[i][5]);
            hh[3] = __floats2half2_rn(acc[i][6], acc[i][7]);
            *reinterpret_cast<uint4*>(&g_m2h[e * DIM + tx * 8]) =
                *reinterpret_cast<uint4*>(hh);
        }
    }
}

// ---- 9) phase2: out[n] = dv^-1/2[n] * Σ_{e∋n} M2h[e]  (warp/node, MLP 8/4) ----
__global__ __launch_bounds__(256)
void phase2_kernel(float* __restrict__ out) {
    int n = (blockIdx.x * blockDim.x + threadIdx.x) >> 5;
    if (n >= NN) return;
    int lane = threadIdx.x & 31;
    const h4* M2 = reinterpret_cast<const h4*>(g_m2h);

    int i = g_noff[n], end = g_noff[n + 1];
    float4 acc = make_float4(0.f, 0.f, 0.f, 0.f);
    for (; i + 8 <= end; i += 8) {
        int c[8];
#pragma unroll
        for (int u = 0; u < 8; u++) c[u] = g_ncols[i + u];
        h4 v[8];
#pragma unroll
        for (int u = 0; u < 8; u++) v[u] = M2[c[u] * 32 + lane];
#pragma unroll
        for (int u = 0; u < 8; u++) {
            float2 a = __half22float2(v[u].a), b = __half22float2(v[u].b);
            acc.x += a.x; acc.y += a.y; acc.z += b.x; acc.w += b.y;
        }
    }
    if (i + 4 <= end) {
        int c[4];
#pragma unroll
        for (int u = 0; u < 4; u++) c[u] = g_ncols[i + u];
        h4 v[4];
#pragma unroll
        for (int u = 0; u < 4; u++) v[u] = M2[c[u] * 32 + lane];
#pragma unroll
        for (int u = 0; u < 4; u++) {
            float2 a = __half22float2(v[u].a), b = __half22float2(v[u].b);
            acc.x += a.x; acc.y += a.y; acc.z += b.x; acc.w += b.y;
        }
        i += 4;
    }
    for (; i < end; i++) {
        h4 v = M2[g_ncols[i] * 32 + lane];
        float2 a = __half22float2(v.a), b = __half22float2(v.b);
        acc.x += a.x; acc.y += a.y; acc.z += b.x; acc.w += b.y;
    }
    float s = g_dvis[n];
    acc.x *= s; acc.y *= s; acc.z *= s; acc.w *= s;
    *(reinterpret_cast<float4*>(out) + n * (DIM / 4) + lane) = acc;
}

extern "C" void kernel_launch(void* const* d_in, const int* in_sizes, int n_in,
                              void* d_out, int out_size) {
    const float* X    = (const float*)d_in[0];
    const int*   rows = (const int*)  d_in[1];
    const int*   cols = (const int*)  d_in[2];
    const float* dv   = (const float*)d_in[3];
    const float* de   = (const float*)d_in[4];
    const float* W    = (const float*)d_in[5];
    float*       out  = (float*)d_out;

    prep_kernel<<<2048, 256>>>(X, dv, de, rows, cols);
    count_kernel<<<1024, 256>>>(rows, cols);
    scanA_kernel<<<NBE + NBN, 1024>>>();
    scanB_kernel<<<1, 32>>>();
    scanC_kernel<<<512, 256>>>();
    fill_kernel<<<1024, 256>>>(rows, cols);

    phase1_kernel<<<(EE * 32 + 255) / 256, 256>>>();

    const size_t GEMM_SMEM = 2 * DIM * DIM * sizeof(float);  // 128 KB
    cudaFuncSetAttribute(gemmE_kernel, cudaFuncAttributeMaxDynamicSharedMemorySize,
                         (int)GEMM_SMEM);
    gemmE_kernel<<<(EE + 127) / 128, 256, GEMM_SMEM>>>(W);

    phase2_kernel<<<((long long)NN * 32 + 255) / 256, 256>>>(out);
}

// round 12
// speedup vs baseline: 1.0521x; 1.0521x over previous
#include <cuda_runtime.h>
#include <cuda_fp16.h>

#define NN   100000
#define EE   20000
#define NNZV 1000000
#define DIM  128

#define NBE 20    // edge scan blocks (EE/1024 rounded up)
#define NBN 98    // node scan blocks (NN/1024 rounded up)

struct alignas(8) h4 { __half2 a, b; };

// ---- scratch: ~50 MB device globals ----
// INVARIANT: g_ecnt/g_ncnt are zero at kernel_launch entry. Static zero-init
// covers the first call; scanBC_kernel re-zeroes them every call after use.
__device__ int    g_ecnt[EE];
__device__ int    g_ncnt[NN];
__device__ int    g_eoff[EE + 1];
__device__ int    g_noff[NN + 1];
__device__ int    g_ecur[EE];
__device__ int    g_ncur[NN];
__device__ int    g_pe[64];
__device__ int    g_pn[128];
__device__ int    g_erows[NNZV];      // CSR by edge: node idx per slot (4 MB)
__device__ int    g_ncols[NNZV];      // CSC by node: edge idx per slot (4 MB)
__device__ __half g_xh[NN * DIM];     // 25.6 MB  fp16(dv^-1/2 * X)
__device__ float  g_m[EE * DIM];      // 10.24 MB fp32 hyperedge features
__device__ __half g_m2h[EE * DIM];    // 5.12 MB  fp16 (m @ W)
__device__ float  g_dvis[NN];         // dv^-1/2
__device__ float  g_deinv[EE];        // de^-1

// ---- 1) prep: scales + X->fp16 + degree histogram (counters zero on entry) ----
__global__ void prep_kernel(const float* __restrict__ X,
                            const float* __restrict__ dv,
                            const float* __restrict__ de,
                            const int*   __restrict__ rows,
                            const int*   __restrict__ cols) {
    int tid = blockIdx.x * blockDim.x + threadIdx.x;
    int stride = gridDim.x * blockDim.x;

    for (int i = tid; i < NN; i += stride) g_dvis[i] = rsqrtf(__ldg(dv + i));
    for (int i = tid; i < EE; i += stride) g_deinv[i] = 1.0f / __ldg(de + i);

    // degree histogram, int4-vectorized (L2-atomic-bound)
    const int4* rows4 = reinterpret_cast<const int4*>(rows);
    const int4* cols4 = reinterpret_cast<const int4*>(cols);
    for (int u = tid; u < NNZV / 4; u += stride) {
        int4 c = __ldg(cols4 + u);
        int4 r = __ldg(rows4 + u);
        atomicAdd(&g_ecnt[c.x], 1); atomicAdd(&g_ecnt[c.y], 1);
        atomicAdd(&g_ecnt[c.z], 1); atomicAdd(&g_ecnt[c.w], 1);
        atomicAdd(&g_ncnt[r.x], 1); atomicAdd(&g_ncnt[r.y], 1);
        atomicAdd(&g_ncnt[r.z], 1); atomicAdd(&g_ncnt[r.w], 1);
    }

    // X -> fp16 with dv^-1/2 folded (HBM-stream-bound; overlaps atomics above)
    const float4* X4 = reinterpret_cast<const float4*>(X);
    h4* Xh = reinterpret_cast<h4*>(g_xh);
    const int UNITS = NN * (DIM / 4);
    for (int u = tid; u < UNITS; u += stride) {
        int r = u >> 5;
        float s = rsqrtf(__ldg(dv + r));
        float4 x = __ldg(X4 + u);
        h4 o;
        o.a = __floats2half2_rn(s * x.x, s * x.y);
        o.b = __floats2half2_rn(s * x.z, s * x.w);
        Xh[u] = o;
    }
}

// ---- 2) scanA: per-1024-block exclusive scan, fused edges+nodes ----
__device__ __forceinline__ void block_scan_body(const int* cnt, int* off,
                                                int* partial, int len, int blk) {
    __shared__ int ws[32];
    int tid = threadIdx.x;
    int lane = tid & 31, wid = tid >> 5;
    int i = blk * 1024 + tid;
    int v = (i < len) ? cnt[i] : 0;
    int sum = v;
#pragma unroll
    for (int d = 1; d < 32; d <<= 1) {
        int t = __shfl_up_sync(0xffffffffu, sum, d);
        if (lane >= d) sum += t;
    }
    if (lane == 31) ws[wid] = sum;
    __syncthreads();
    if (wid == 0) {
        int wsum = ws[lane];
#pragma unroll
        for (int d = 1; d < 32; d <<= 1) {
            int t = __shfl_up_sync(0xffffffffu, wsum, d);
            if (lane >= d) wsum += t;
        }
        ws[lane] = wsum;
    }
    __syncthreads();
    int incl = sum + (wid > 0 ? ws[wid - 1] : 0);
    if (i < len) off[i] = incl - v;
    if (tid == 1023) partial[blk] = incl;
}
__global__ void scanA_kernel() {
    if (blockIdx.x < NBE)
        block_scan_body(g_ecnt, g_eoff, g_pe, EE, blockIdx.x);
    else
        block_scan_body(g_ncnt, g_noff, g_pn, NN, blockIdx.x - NBE);
}

// ---- 3) scanBC: each block computes its partial-prefix in-warp, finalizes
//         offsets + cursors, and re-zeroes the counters (next-call invariant) ----
__global__ void scanBC_kernel() {
    __shared__ int s_base;
    int b = blockIdx.x;
    bool is_edge = (b < NBE);
    int blk = is_edge ? b : b - NBE;
    const int* part = is_edge ? g_pe : g_pn;

    int tid = threadIdx.x;
    if (tid < 32) {
        int s = 0;
#pragma unroll
        for (int k = 0; k < 4; k++) {
            int idx = tid + k * 32;
            if (idx < blk) s += part[idx];
        }
#pragma unroll
        for (int d = 16; d > 0; d >>= 1)
            s += __shfl_xor_sync(0xffffffffu, s, d);
        if (tid == 0) s_base = s;
    }
    __syncthreads();
    int base = s_base;

    int i = blk * 1024 + tid;
    if (is_edge) {
        if (i < EE) {
            int o = g_eoff[i] + base;
            g_eoff[i] = o;
            g_ecur[i] = o;
            g_ecnt[i] = 0;            // restore invariant
        }
        if (b == 0 && tid == 0) { g_eoff[EE] = NNZV; g_noff[NN] = NNZV; }
    } else {
        if (i < NN) {
            int o = g_noff[i] + base;
            g_noff[i] = o;
            g_ncur[i] = o;
            g_ncnt[i] = 0;            // restore invariant
        }
    }
}

// ---- 4) fill buckets (int4-vectorized index loads) ----
__global__ void fill_kernel(const int* __restrict__ rows,
                            const int* __restrict__ cols) {
    int tid = blockIdx.x * blockDim.x + threadIdx.x;
    int stride = gridDim.x * blockDim.x;
    const int4* rows4 = reinterpret_cast<const int4*>(rows);
    const int4* cols4 = reinterpret_cast<const int4*>(cols);
    for (int u = tid; u < NNZV / 4; u += stride) {
        int4 r = __ldg(rows4 + u);
        int4 c = __ldg(cols4 + u);
        int p0 = atomicAdd(&g_ecur[c.x], 1);
        int p1 = atomicAdd(&g_ecur[c.y], 1);
        int p2 = atomicAdd(&g_ecur[c.z], 1);
        int p3 = atomicAdd(&g_ecur[c.w], 1);
        g_erows[p0] = r.x; g_erows[p1] = r.y; g_erows[p2] = r.z; g_erows[p3] = r.w;
        int q0 = atomicAdd(&g_ncur[r.x], 1);
        int q1 = atomicAdd(&g_ncur[r.y], 1);
        int q2 = atomicAdd(&g_ncur[r.z], 1);
        int q3 = atomicAdd(&g_ncur[r.w], 1);
        g_ncols[q0] = c.x; g_ncols[q1] = c.y; g_ncols[q2] = c.z; g_ncols[q3] = c.w;
    }
}

// ---- 5) phase1: m[e] = de^-1 * Σ_{r∈e} Xh[r]  (warp/edge, fp16, MLP=8) ----
__global__ __launch_bounds__(256)
void phase1_kernel() {
    int e = (blockIdx.x * blockDim.x + threadIdx.x) >> 5;
    if (e >= EE) return;
    int lane = threadIdx.x & 31;
    const h4* Xh = reinterpret_cast<const h4*>(g_xh);

    int i = g_eoff[e], end = g_eoff[e + 1];
    float4 acc = make_float4(0.f, 0.f, 0.f, 0.f);
    for (; i + 8 <= end; i += 8) {
        int r[8];
#pragma unroll
        for (int u = 0; u < 8; u++) r[u] = g_erows[i + u];
        h4 v[8];
#pragma unroll
        for (int u = 0; u < 8; u++) v[u] = Xh[r[u] * 32 + lane];
#pragma unroll
        for (int u = 0; u < 8; u++) {
            float2 a = __half22float2(v[u].a), b = __half22float2(v[u].b);
            acc.x += a.x; acc.y += a.y; acc.z += b.x; acc.w += b.y;
        }
    }
    if (i + 4 <= end) {
        int r[4];
#pragma unroll
        for (int u = 0; u < 4; u++) r[u] = g_erows[i + u];
        h4 v[4];
#pragma unroll
        for (int u = 0; u < 4; u++) v[u] = Xh[r[u] * 32 + lane];
#pragma unroll
        for (int u = 0; u < 4; u++) {
            float2 a = __half22float2(v[u].a), b = __half22float2(v[u].b);
            acc.x += a.x; acc.y += a.y; acc.z += b.x; acc.w += b.y;
        }
        i += 4;
    }
    for (; i < end; i++) {
        h4 v = Xh[g_erows[i] * 32 + lane];
        float2 a = __half22float2(v.a), b = __half22float2(v.b);
        acc.x += a.x; acc.y += a.y; acc.z += b.x; acc.w += b.y;
    }
    float d = g_deinv[e];
    acc.x *= d; acc.y *= d; acc.z *= d; acc.w *= d;
    *(reinterpret_cast<float4*>(g_m) + e * (DIM / 4) + lane) = acc;
}

// ---- 6) gemmE: M2h = fp16(m @ W)  BM=128, 8x8 micro ----
__global__ __launch_bounds__(256, 1)
void gemmE_kernel(const float* __restrict__ W) {
    extern __shared__ float smem[];
    float* Yt = smem;                 // [DIM][DIM] k-major
    float* Ws = smem + DIM * DIM;     // [DIM][DIM] row-major

    int tid = threadIdx.x;
    int block_row = blockIdx.x * 128;

    for (int i = tid; i < DIM * (DIM / 4); i += 256) {
        int r = i >> 5, c4 = i & 31;
        float4 v = __ldg(reinterpret_cast<const float4*>(W) + r * (DIM / 4) + c4);
        *reinterpret_cast<float4*>(&Ws[r * DIM + c4 * 4]) = v;
    }
    for (int i = tid; i < (DIM / 4) * DIM; i += 256) {
        int r = i & 127, c4 = i >> 7;
        int e = block_row + r;
        float4 v = make_float4(0.f, 0.f, 0.f, 0.f);
        if (e < EE)
            v = *(reinterpret_cast<const float4*>(g_m) + e * (DIM / 4) + c4);
        Yt[(c4 * 4 + 0) * DIM + r] = v.x;
        Yt[(c4 * 4 + 1) * DIM + r] = v.y;
        Yt[(c4 * 4 + 2) * DIM + r] = v.z;
        Yt[(c4 * 4 + 3) * DIM + r] = v.w;
    }
    __syncthreads();

    int tx = tid & 15;
    int ty = tid >> 4;

    float acc[8][8];
#pragma unroll
    for (int i = 0; i < 8; i++)
#pragma unroll
        for (int j = 0; j < 8; j++) acc[i][j] = 0.f;

#pragma unroll 4
    for (int k = 0; k < DIM; k++) {
        float yf[8], wf[8];
        *reinterpret_cast<float4*>(&yf[0]) = *reinterpret_cast<float4*>(&Yt[k * DIM + ty * 8]);
        *reinterpret_cast<float4*>(&yf[4]) = *reinterpret_cast<float4*>(&Yt[k * DIM + ty * 8 + 4]);
        *reinterpret_cast<float4*>(&wf[0]) = *reinterpret_cast<float4*>(&Ws[k * DIM + tx * 8]);
        *reinterpret_cast<float4*>(&wf[4]) = *reinterpret_cast<float4*>(&Ws[k * DIM + tx * 8 + 4]);
#pragma unroll
        for (int i = 0; i < 8; i++)
#pragma unroll
            for (int j = 0; j < 8; j++)
                acc[i][j] += yf[i] * wf[j];
    }

#pragma unroll
    for (int i = 0; i < 8; i++) {
        int e = block_row + ty * 8 + i;
        if (e < EE) {
            alignas(16) __half2 hh[4];
            hh[0] = __floats2half2_rn(acc[i][0], acc[i][1]);
            hh[1] = __floats2half2_rn(acc[i][2], acc[i][3]);
            hh[2] = __floats2half2_rn(acc[i][4], acc[i][5]);
            hh[3] = __floats2half2_rn(acc[i][6], acc[i][7]);
            *reinterpret_cast<uint4*>(&g_m2h[e * DIM + tx * 8]) =
                *reinterpret_cast<uint4*>(hh);
        }
    }
}

// ---- 7) phase2: out[n] = dv^-1/2[n] * Σ_{e∋n} M2h[e]  (warp/node, MLP 8/4) ----
__global__ __launch_bounds__(256)
void phase2_kernel(float* __restrict__ out) {
    int n = (blockIdx.x * blockDim.x + threadIdx.x) >> 5;
    if (n >= NN) return;
    int lane = threadIdx.x & 31;
    const h4* M2 = reinterpret_cast<const h4*>(g_m2h);

    int i = g_noff[n], end = g_noff[n + 1];
    float4 acc = make_float4(0.f, 0.f, 0.f, 0.f);
    for (; i + 8 <= end; i += 8) {
        int c[8];
#pragma unroll
        for (int u = 0; u < 8; u++) c[u] = g_ncols[i + u];
        h4 v[8];
#pragma unroll
        for (int u = 0; u < 8; u++) v[u] = M2[c[u] * 32 + lane];
#pragma unroll
        for (int u = 0; u < 8; u++) {
            float2 a = __half22float2(v[u].a), b = __half22float2(v[u].b);
            acc.x += a.x; acc.y += a.y; acc.z += b.x; acc.w += b.y;
        }
    }
    if (i + 4 <= end) {
        int c[4];
#pragma unroll
        for (int u = 0; u < 4; u++) c[u] = g_ncols[i + u];
        h4 v[4];
#pragma unroll
        for (int u = 0; u < 4; u++) v[u] = M2[c[u] * 32 + lane];
#pragma unroll
        for (int u = 0; u < 4; u++) {
            float2 a = __half22float2(v[u].a), b = __half22float2(v[u].b);
            acc.x += a.x; acc.y += a.y; acc.z += b.x; acc.w += b.y;
        }
        i += 4;
    }
    for (; i < end; i++) {
        h4 v = M2[g_ncols[i] * 32 + lane];
        float2 a = __half22float2(v.a), b = __half22float2(v.b);
        acc.x += a.x; acc.y += a.y; acc.z += b.x; acc.w += b.y;
    }
    float s = g_dvis[n];
    acc.x *= s; acc.y *= s; acc.z *= s; acc.w *= s;
    *(reinterpret_cast<float4*>(out) + n * (DIM / 4) + lane) = acc;
}

extern "C" void kernel_launch(void* const* d_in, const int* in_sizes, int n_in,
                              void* d_out, int out_size) {
    const float* X    = (const float*)d_in[0];
    const int*   rows = (const int*)  d_in[1];
    const int*   cols = (const int*)  d_in[2];
    const float* dv   = (const float*)d_in[3];
    const float* de   = (const float*)d_in[4];
    const float* W    = (const float*)d_in[5];
    float*       out  = (float*)d_out;

    prep_kernel<<<2048, 256>>>(X, dv, de, rows, cols);
    scanA_kernel<<<NBE + NBN, 1024>>>();
    scanBC_kernel<<<NBE + NBN, 1024>>>();
    fill_kernel<<<1024, 256>>>(rows, cols);

    phase1_kernel<<<(EE * 32 + 255) / 256, 256>>>();

    const size_t GEMM_SMEM = 2 * DIM * DIM * sizeof(float);  // 128 KB
    cudaFuncSetAttribute(gemmE_kernel, cudaFuncAttributeMaxDynamicSharedMemorySize,
                         (int)GEMM_SMEM);
    gemmE_kernel<<<(EE + 127) / 128, 256, GEMM_SMEM>>>(W);

    phase2_kernel<<<((long long)NN * 32 + 255) / 256, 256>>>(out);
}